// round 11
// baseline (speedup 1.0000x reference)
#include <cuda_runtime.h>
#include <cstdint>

// Pair_83811991814342
// in:  (1, 1024, 260) fp32; only first 512 rows used
// out: (1, 512*512, 522) fp32 : [x[i](260) | x[j](260) | r1 | r2]
// Strategy: stage 8 contiguous output rows (16704 B) in smem, write via
// cp.async.bulk (TMA bulk store), double-buffered.

#define NROWS 512
#define DIM   260
#define ROWB  2088                  // output bytes per row (522 * 4)
#define GRPB  (8 * ROWB)            // 16704 B per il-group (mult of 16)
#define NT    256

__device__ __forceinline__ uint32_t smem_u32(const void* p) {
    uint32_t a;
    asm("{ .reg .u64 t; cvta.to.shared.u64 t, %1; cvt.u32.u64 %0, t; }"
        : "=r"(a) : "l"(p));
    return a;
}

__global__ __launch_bounds__(NT)
void pair_kernel(const float* __restrict__ in, float* __restrict__ out) {
    __shared__ __align__(16) char s_buf[2][GRPB];   // double-buffered il-group
    __shared__ float2 s_r[64];                      // (r1, r2) per (il, jl)

    const int bi = blockIdx.y * 8;
    const int bj = blockIdx.x * 8;
    const int t  = threadIdx.x;

    // ---- Threads 0..63: (r1, r2) table ----
    if (t < 64) {
        int il = t >> 3, jl = t & 7;
        const float4 a = __ldg(reinterpret_cast<const float4*>(
            in + (bi + il) * DIM + (DIM - 4)));
        const float4 b = __ldg(reinterpret_cast<const float4*>(
            in + (bj + jl) * DIM + (DIM - 4)));
        float w = fmaxf(0.0f, fminf(a.z, b.z) - fmaxf(a.x, b.x));
        float h = fmaxf(0.0f, fminf(a.w, b.w) - fmaxf(a.y, b.y));
        float inter = w * h;
        s_r[t] = make_float2(inter / ((a.z - a.x) * (a.w - a.y)),
                             inter / ((b.z - b.x) * (b.w - b.y)));
    }
    __syncthreads();

    const float2* inI = reinterpret_cast<const float2*>(in + (size_t)bi * DIM);
    const float2* inJ = reinterpret_cast<const float2*>(in + (size_t)bj * DIM);

    for (int il = 0; il < 8; il++) {
        if (il >= 2) {
            // recycle buffer (il-2)'s smem: wait until TMA finished reading it
            if (t == 0)
                asm volatile("cp.async.bulk.wait_group.read 1;" ::: "memory");
            __syncthreads();
        }
        char* buf = s_buf[il & 1];
        const float2* rowI = inI + (size_t)il * (DIM / 2);

        // ---- Fill 8 output rows (2088 float2 stores across the block) ----
        for (int u = t; u < 8 * 261; u += NT) {
            int jl = u / 261;
            int c  = u - 261 * jl;
            float2 v;
            if (c < 130)       v = __ldg(&rowI[c]);
            else if (c < 260)  v = __ldg(&inJ[(size_t)jl * (DIM / 2) + (c - 130)]);
            else               v = s_r[(il << 3) | jl];
            *reinterpret_cast<float2*>(buf + jl * ROWB + c * 8) = v;
        }
        __syncthreads();

        // ---- One bulk store: 16704 B smem -> gmem (contiguous 8 rows) ----
        if (t == 0) {
            asm volatile("fence.proxy.async.shared::cta;" ::: "memory");
            const float* gdst = out + ((size_t)(bi + il) * NROWS + bj) * 522;
            asm volatile(
                "cp.async.bulk.global.shared::cta.bulk_group [%0], [%1], %2;"
                :: "l"(gdst), "r"(smem_u32(buf)), "r"((uint32_t)GRPB)
                : "memory");
            asm volatile("cp.async.bulk.commit_group;" ::: "memory");
        }
    }

    // Drain all pending bulk stores before exit
    if (t == 0)
        asm volatile("cp.async.bulk.wait_group 0;" ::: "memory");
}

extern "C" void kernel_launch(void* const* d_in, const int* in_sizes, int n_in,
                              void* d_out, int out_size) {
    const float* in = (const float*)d_in[0];
    float* out = (float*)d_out;
    dim3 grid(NROWS / 8, NROWS / 8);  // 64 x 64 blocks
    pair_kernel<<<grid, NT>>>(in, out);
}

// round 12
// speedup vs baseline: 1.3648x; 1.3648x over previous
#include <cuda_runtime.h>
#include <cstdint>

// Pair_83811991814342
// in:  (1, 1024, 260) fp32; only first 512 rows used
// out: (1, 512*512, 522) fp32 : [x[i](260) | x[j](260) | r1 | r2]
// TMA bulk-store pipeline, round 2: cheap column-per-thread fill.

#define NROWS 512
#define DIM   260
#define ROWB  2088                  // output bytes per row
#define GRPB  (8 * ROWB)            // 16704 B per il-group
#define NT    288

__device__ __forceinline__ uint32_t smem_u32(const void* p) {
    uint32_t a;
    asm("{ .reg .u64 t; cvta.to.shared.u64 t, %1; cvt.u32.u64 %0, t; }"
        : "=r"(a) : "l"(p));
    return a;
}

__global__ __launch_bounds__(NT)
void pair_kernel(const float* __restrict__ in, float* __restrict__ out) {
    __shared__ __align__(16) char s_buf[2][GRPB];   // double-buffered il-group
    __shared__ float2 s_r[64];                      // (r1, r2) per (il, jl)

    const int bi = blockIdx.y * 8;
    const int bj = blockIdx.x * 8;
    const int t  = threadIdx.x;

    // ---- Threads 0..63: (r1, r2) table ----
    if (t < 64) {
        int il = t >> 3, jl = t & 7;
        const float4 a = __ldg(reinterpret_cast<const float4*>(
            in + (bi + il) * DIM + (DIM - 4)));
        const float4 b = __ldg(reinterpret_cast<const float4*>(
            in + (bj + jl) * DIM + (DIM - 4)));
        float w = fmaxf(0.0f, fminf(a.z, b.z) - fmaxf(a.x, b.x));
        float h = fmaxf(0.0f, fminf(a.w, b.w) - fmaxf(a.y, b.y));
        float inter = w * h;
        s_r[t] = make_float2(inter / ((a.z - a.x) * (a.w - a.y)),
                             inter / ((b.z - b.x) * (b.w - b.y)));
    }
    __syncthreads();

    const int c = t;                                // float2 column [0,261)
    const float2* inI = reinterpret_cast<const float2*>(in) + (size_t)bi * (DIM / 2);
    const float2* inJ = reinterpret_cast<const float2*>(in) + (size_t)bj * (DIM / 2);

    // j-part values are il-invariant: preload 8 float2 into registers.
    float2 vJ[8];
    const bool isI = (c < 130);
    const bool isJ = (c >= 130) && (c < 260);
    if (isJ) {
        #pragma unroll
        for (int jl = 0; jl < 8; jl++)
            vJ[jl] = __ldg(&inJ[(size_t)jl * (DIM / 2) + (c - 130)]);
    }

    for (int il = 0; il < 8; il++) {
        if (il >= 2) {
            // recycle s_buf[il&1]: wait until TMA finished reading it
            if (t == 0)
                asm volatile("cp.async.bulk.wait_group.read 1;" ::: "memory");
            __syncthreads();
        }
        char* const buf = s_buf[il & 1];

        if (c < 261) {
            float2 vI = make_float2(0.f, 0.f);
            if (isI) vI = __ldg(&inI[(size_t)il * (DIM / 2) + c]);
            char* p = buf + c * 8;
            #pragma unroll
            for (int jl = 0; jl < 8; jl++) {
                float2 v = isI ? vI : (isJ ? vJ[jl] : s_r[(il << 3) | jl]);
                *reinterpret_cast<float2*>(p + jl * ROWB) = v;
            }
        }
        __syncthreads();

        // ---- One bulk store: 16704 B smem -> gmem (8 contiguous rows) ----
        if (t == 0) {
            asm volatile("fence.proxy.async.shared::cta;" ::: "memory");
            const float* gdst = out + ((size_t)(bi + il) * NROWS + bj) * 522;
            asm volatile(
                "cp.async.bulk.global.shared::cta.bulk_group [%0], [%1], %2;"
                :: "l"(gdst), "r"(smem_u32(buf)), "r"((uint32_t)GRPB)
                : "memory");
            asm volatile("cp.async.bulk.commit_group;" ::: "memory");
        }
    }

    // Drain all pending bulk stores before exit
    if (t == 0)
        asm volatile("cp.async.bulk.wait_group 0;" ::: "memory");
}

extern "C" void kernel_launch(void* const* d_in, const int* in_sizes, int n_in,
                              void* d_out, int out_size) {
    const float* in = (const float*)d_in[0];
    float* out = (float*)d_out;
    dim3 grid(NROWS / 8, NROWS / 8);  // 64 x 64 blocks
    pair_kernel<<<grid, NT>>>(in, out);
}

// round 13
// speedup vs baseline: 1.3971x; 1.0237x over previous
#include <cuda_runtime.h>
#include <cstdint>

// Pair_83811991814342
// in:  (1, 1024, 260) fp32; only first 512 rows used
// out: (1, 512*512, 522) fp32 : [x[i](260) | x[j](260) | r1 | r2]
// TMA bulk-store pipeline, 4-deep: 4 staging buffers of 4 output rows each.

#define NROWS 512
#define DIM   260
#define ROWB  2088                  // output bytes per row
#define RPG   4                     // rows per group
#define GRPB  (RPG * ROWB)          // 8352 B per group (mult 16; base 16-aligned)
#define NBUF  4
#define NT    288

__device__ __forceinline__ uint32_t smem_u32(const void* p) {
    uint32_t a;
    asm("{ .reg .u64 t; cvta.to.shared.u64 t, %1; cvt.u32.u64 %0, t; }"
        : "=r"(a) : "l"(p));
    return a;
}

__global__ __launch_bounds__(NT, 6)
void pair_kernel(const float* __restrict__ in, float* __restrict__ out) {
    __shared__ __align__(16) char s_buf[NBUF][GRPB];
    __shared__ float2 s_r[64];                      // (r1, r2) per (il, jl)

    const int bi = blockIdx.y * 8;
    const int bj = blockIdx.x * 8;
    const int t  = threadIdx.x;

    // ---- Threads 0..63: (r1, r2) table ----
    if (t < 64) {
        int il = t >> 3, jl = t & 7;
        const float4 a = __ldg(reinterpret_cast<const float4*>(
            in + (bi + il) * DIM + (DIM - 4)));
        const float4 b = __ldg(reinterpret_cast<const float4*>(
            in + (bj + jl) * DIM + (DIM - 4)));
        float w = fmaxf(0.0f, fminf(a.z, b.z) - fmaxf(a.x, b.x));
        float h = fmaxf(0.0f, fminf(a.w, b.w) - fmaxf(a.y, b.y));
        float inter = w * h;
        s_r[t] = make_float2(inter / ((a.z - a.x) * (a.w - a.y)),
                             inter / ((b.z - b.x) * (b.w - b.y)));
    }
    __syncthreads();

    const int c = t;                                // float2 column [0,261)
    const bool isI = (c < 130);
    const bool isJ = (c >= 130) && (c < 260);
    const float2* inI = reinterpret_cast<const float2*>(in) + (size_t)bi * (DIM / 2);
    const float2* inJ = reinterpret_cast<const float2*>(in) + (size_t)bj * (DIM / 2);

    // j-part values are il-invariant: preload 8 float2 into registers.
    float2 vJ[8];
    if (isJ) {
        #pragma unroll
        for (int jl = 0; jl < 8; jl++)
            vJ[jl] = __ldg(&inJ[(size_t)jl * (DIM / 2) + (c - 130)]);
    }

    // 16 groups: group g = (il = g/2, jl in [4*(g&1), 4*(g&1)+4))
    for (int g = 0; g < 16; g++) {
        const int il = g >> 1;
        const int hb = g & 1;                        // jl half: 0 -> 0..3, 1 -> 4..7
        if (g >= NBUF) {
            if (t == 0)
                asm volatile("cp.async.bulk.wait_group.read 3;" ::: "memory");
            __syncthreads();
        }
        char* const buf = s_buf[g & (NBUF - 1)];

        if (c < 261) {
            float2 vI = make_float2(0.f, 0.f);
            if (isI) vI = __ldg(&inI[(size_t)il * (DIM / 2) + c]);
            char* p = buf + c * 8;
            #pragma unroll
            for (int k = 0; k < 4; k++) {
                const int jl4 = 4 * hb + k;
                float2 vj = hb ? vJ[k + 4] : vJ[k];  // compile-time reg index
                float2 v  = isI ? vI : (isJ ? vj : s_r[(il << 3) | jl4]);
                *reinterpret_cast<float2*>(p + k * ROWB) = v;
            }
        }
        __syncthreads();

        // ---- One bulk store: 8352 B smem -> gmem (4 contiguous rows) ----
        if (t == 0) {
            asm volatile("fence.proxy.async.shared::cta;" ::: "memory");
            const float* gdst = out
                + ((size_t)(bi + il) * NROWS + bj + 4 * hb) * 522;
            asm volatile(
                "cp.async.bulk.global.shared::cta.bulk_group [%0], [%1], %2;"
                :: "l"(gdst), "r"(smem_u32(buf)), "r"((uint32_t)GRPB)
                : "memory");
            asm volatile("cp.async.bulk.commit_group;" ::: "memory");
        }
    }

    // Drain all pending bulk stores before exit
    if (t == 0)
        asm volatile("cp.async.bulk.wait_group 0;" ::: "memory");
}

extern "C" void kernel_launch(void* const* d_in, const int* in_sizes, int n_in,
                              void* d_out, int out_size) {
    const float* in = (const float*)d_in[0];
    float* out = (float*)d_out;
    dim3 grid(NROWS / 8, NROWS / 8);  // 64 x 64 blocks
    pair_kernel<<<grid, NT>>>(in, out);
}

// round 14
// speedup vs baseline: 1.4048x; 1.0055x over previous
#include <cuda_runtime.h>
#include <cstdint>

// Pair_83811991814342
// in:  (1, 1024, 260) fp32; only first 512 rows used
// out: (1, 512*512, 522) fp32 : [x[i](260) | x[j](260) | r1 | r2]
// TMA bulk-store pipeline, 4-deep, with all input loads hoisted to registers.

#define NROWS 512
#define DIM   260
#define ROWB  2088                  // output bytes per row
#define RPG   4                     // rows per group
#define GRPB  (RPG * ROWB)          // 8352 B per group
#define NBUF  4
#define NT    288

__device__ __forceinline__ uint32_t smem_u32(const void* p) {
    uint32_t a;
    asm("{ .reg .u64 t; cvta.to.shared.u64 t, %1; cvt.u32.u64 %0, t; }"
        : "=r"(a) : "l"(p));
    return a;
}

__global__ __launch_bounds__(NT, 6)
void pair_kernel(const float* __restrict__ in, float* __restrict__ out) {
    __shared__ __align__(16) char s_buf[NBUF][GRPB];
    __shared__ float2 s_r[64];                      // (r1, r2) per (il, jl)

    const int bi = blockIdx.y * 8;
    const int bj = blockIdx.x * 8;
    const int t  = threadIdx.x;

    // ---- Threads 0..63: (r1, r2) table ----
    if (t < 64) {
        int il = t >> 3, jl = t & 7;
        const float4 a = __ldg(reinterpret_cast<const float4*>(
            in + (bi + il) * DIM + (DIM - 4)));
        const float4 b = __ldg(reinterpret_cast<const float4*>(
            in + (bj + jl) * DIM + (DIM - 4)));
        float w = fmaxf(0.0f, fminf(a.z, b.z) - fmaxf(a.x, b.x));
        float h = fmaxf(0.0f, fminf(a.w, b.w) - fmaxf(a.y, b.y));
        float inter = w * h;
        s_r[t] = make_float2(inter / ((a.z - a.x) * (a.w - a.y)),
                             inter / ((b.z - b.x) * (b.w - b.y)));
    }
    __syncthreads();

    const int c = t;                                // float2 column [0,261)
    const bool isI = (c < 130);
    const bool isJ = (c >= 130) && (c < 260);

    // ---- Hoisted preload: thread's 8 values (i-rows or j-rows) in registers ----
    float2 v[8];
    if (c < 260) {
        const float2* base = reinterpret_cast<const float2*>(in)
            + (isI ? ((size_t)bi * (DIM / 2) + c)
                   : ((size_t)bj * (DIM / 2) + (c - 130)));
        #pragma unroll
        for (int r = 0; r < 8; r++)
            v[r] = __ldg(&base[(size_t)r * (DIM / 2)]);
    }

    // 16 groups, fully unrolled: group g = (il = g/2, jl in [4*(g&1), +4))
    #pragma unroll
    for (int g = 0; g < 16; g++) {
        const int il = g >> 1;
        const int hb = g & 1;
        if (g >= NBUF) {
            if (t == 0)
                asm volatile("cp.async.bulk.wait_group.read 3;" ::: "memory");
            __syncthreads();
        }
        char* const buf = s_buf[g & (NBUF - 1)];

        if (c < 261) {
            char* p = buf + c * 8;
            #pragma unroll
            for (int k = 0; k < 4; k++) {
                const int jl4 = 4 * hb + k;
                float2 val;
                if (isI)      val = v[il];          // compile-time reg index
                else if (isJ) val = v[jl4];         // compile-time reg index
                else          val = s_r[(il << 3) | jl4];
                *reinterpret_cast<float2*>(p + k * ROWB) = val;
            }
        }
        __syncthreads();

        // ---- One bulk store: 8352 B smem -> gmem (4 contiguous rows) ----
        if (t == 0) {
            asm volatile("fence.proxy.async.shared::cta;" ::: "memory");
            const float* gdst = out
                + ((size_t)(bi + il) * NROWS + bj + 4 * hb) * 522;
            asm volatile(
                "cp.async.bulk.global.shared::cta.bulk_group [%0], [%1], %2;"
                :: "l"(gdst), "r"(smem_u32(buf)), "r"((uint32_t)GRPB)
                : "memory");
            asm volatile("cp.async.bulk.commit_group;" ::: "memory");
        }
    }

    // Drain all pending bulk stores before exit
    if (t == 0)
        asm volatile("cp.async.bulk.wait_group 0;" ::: "memory");
}

extern "C" void kernel_launch(void* const* d_in, const int* in_sizes, int n_in,
                              void* d_out, int out_size) {
    const float* in = (const float*)d_in[0];
    float* out = (float*)d_out;
    dim3 grid(NROWS / 8, NROWS / 8);  // 64 x 64 blocks
    pair_kernel<<<grid, NT>>>(in, out);
}